// round 2
// baseline (speedup 1.0000x reference)
#include <cuda_runtime.h>
#include <math.h>

// Problem dims
#define DM   1024          // d_model
#define G4   4096          // 4*d_model
#define NB   128           // batch
#define NS   1024          // seq
#define NC   512           // n_classes
#define NCTA 128           // persistent CTAs (one per 8 d-values)

// ---------------- device scratch (static, no allocation) ----------------
__device__ float g_G[NC * G4];            // 8 MB: G = emb @ W_ih^T + b_ih + b_hh
__device__ float g_hist[NS * NB * DM];    // 512 MB: all h outputs
__device__ int   g_bar[NS];               // grid-barrier counters (reset each launch)

// =========================================================================
// Generic NT GEMM: C[M,N] = A[M,K] @ B[N,K]^T + bias
// Tile 64x64, BK=16, 256 threads, 4x4 microtile.
// MODE 0: C[m*N+n] = acc + bias0[n] + bias1[n]          (for G)
// MODE 1: logits remap: row=(s*128+b) -> out[b*NS*NC + s*NC + n] = acc + bias0[n]
// =========================================================================
template <int MODE>
__global__ void gemm_nt_kernel(const float* __restrict__ A,
                               const float* __restrict__ Bm,
                               const float* __restrict__ bias0,
                               const float* __restrict__ bias1,
                               float* __restrict__ Cout,
                               int M, int N, int K)
{
    __shared__ float As[16][64];
    __shared__ float Bs[16][64];

    const int tid = threadIdx.x;
    const int tx  = tid & 15;
    const int ty  = tid >> 4;
    const int mBase = blockIdx.x * 64;
    const int nBase = blockIdx.y * 64;

    const int la  = tid >> 2;
    const int lk  = (tid & 3) * 4;

    float acc[4][4];
#pragma unroll
    for (int i = 0; i < 4; i++)
#pragma unroll
        for (int j = 0; j < 4; j++) acc[i][j] = 0.f;

    for (int kc = 0; kc < K; kc += 16) {
        {
            float4 v = *reinterpret_cast<const float4*>(&A[(size_t)(mBase + la) * K + kc + lk]);
            As[lk + 0][la] = v.x; As[lk + 1][la] = v.y;
            As[lk + 2][la] = v.z; As[lk + 3][la] = v.w;
        }
        {
            float4 v = *reinterpret_cast<const float4*>(&Bm[(size_t)(nBase + la) * K + kc + lk]);
            Bs[lk + 0][la] = v.x; Bs[lk + 1][la] = v.y;
            Bs[lk + 2][la] = v.z; Bs[lk + 3][la] = v.w;
        }
        __syncthreads();

#pragma unroll
        for (int k = 0; k < 16; k++) {
            float4 a4 = *reinterpret_cast<const float4*>(&As[k][tx * 4]);
            float4 b4 = *reinterpret_cast<const float4*>(&Bs[k][ty * 4]);
            float a[4] = {a4.x, a4.y, a4.z, a4.w};
            float b[4] = {b4.x, b4.y, b4.z, b4.w};
#pragma unroll
            for (int i = 0; i < 4; i++)
#pragma unroll
                for (int j = 0; j < 4; j++)
                    acc[i][j] = fmaf(a[i], b[j], acc[i][j]);
        }
        __syncthreads();
    }

#pragma unroll
    for (int i = 0; i < 4; i++) {
        int row = mBase + tx * 4 + i;
#pragma unroll
        for (int j = 0; j < 4; j++) {
            int col = nBase + ty * 4 + j;
            if (MODE == 0) {
                Cout[(size_t)row * N + col] = acc[i][j] + bias0[col] + bias1[col];
            } else {
                int s_ = row >> 7;
                int bb = row & 127;
                Cout[(size_t)bb * NS * NC + (size_t)s_ * NC + col] = acc[i][j] + bias0[col];
            }
        }
    }
}

// =========================================================================
// Persistent LSTM kernel: 128 CTAs x 256 threads, one CTA per 8 d-values.
// W_hh slice (32 rows x 1024) lives in SMEM for all 1024 steps.
// Per step: gates = G[x[s,b]] + h_{s-1} @ W_slice^T, cell update (c in regs),
// h written to g_hist[s], then software grid barrier.
// =========================================================================
__global__ void __launch_bounds__(256, 1)
lstm_persistent_kernel(const int* __restrict__ x,
                       const float* __restrict__ Whh)
{
    extern __shared__ float smem[];
    float* ws = smem;             // [1024][32] W slice, k-major
    float* hs = smem + 32768;     // 2 x [32][128] h staging buffers

    const int tid = threadIdx.x;
    const int d0  = blockIdx.x * 8;
    const int tx  = tid & 31;          // batch group
    const int ty  = tid >> 5;          // row group
    const int b0  = tx * 4;
    const int r0  = ty * 4;

    // ---- preload W slice into smem (one-time) ----
    {
        const int k0 = tid * 4;
#pragma unroll 4
        for (int lr = 0; lr < 32; lr++) {
            int grow_ = (lr >> 3) * DM + d0 + (lr & 7);   // gate-major global row
            float4 v = *reinterpret_cast<const float4*>(&Whh[(size_t)grow_ * DM + k0]);
            ws[(k0 + 0) * 32 + lr] = v.x;
            ws[(k0 + 1) * 32 + lr] = v.y;
            ws[(k0 + 2) * 32 + lr] = v.z;
            ws[(k0 + 3) * 32 + lr] = v.w;
        }
    }

    // ---- persistent per-thread state ----
    const int cb  = tid >> 1;          // batch owned for cell update
    const int dl0 = (tid & 1) * 4;     // local d offset (0 or 4)
    float cr[4] = {0.f, 0.f, 0.f, 0.f};

    // staging loader indices
    const int lb = tid >> 1;           // h row (batch) 0..127
    const int lk = (tid & 1) * 16;     // k sub-offset within 32-chunk

    __syncthreads();

    for (int s = 0; s < NS; s++) {
        float acc[4][4];
#pragma unroll
        for (int i = 0; i < 4; i++)
#pragma unroll
            for (int j = 0; j < 4; j++) acc[i][j] = 0.f;

        if (s > 0) {
            const float* hprev = &g_hist[(size_t)(s - 1) * NB * DM];

            // prefetch + stage chunk 0 into buffer 0
            float4 pv[4];
            {
                const float* hrow = &hprev[(size_t)lb * DM + lk];
#pragma unroll
                for (int i = 0; i < 4; i++)
                    pv[i] = *reinterpret_cast<const float4*>(&hrow[i * 4]);
#pragma unroll
                for (int i = 0; i < 4; i++) {
                    int kl = lk + i * 4;
                    hs[(kl + 0) * 128 + lb] = pv[i].x;
                    hs[(kl + 1) * 128 + lb] = pv[i].y;
                    hs[(kl + 2) * 128 + lb] = pv[i].z;
                    hs[(kl + 3) * 128 + lb] = pv[i].w;
                }
            }

            int cur = 0;
            for (int kc = 0; kc < DM; kc += 32) {
                __syncthreads();   // buffer 'cur' ready

                const bool more = (kc + 32 < DM);
                if (more) {
                    const float* hrow = &hprev[(size_t)lb * DM + kc + 32 + lk];
#pragma unroll
                    for (int i = 0; i < 4; i++)
                        pv[i] = *reinterpret_cast<const float4*>(&hrow[i * 4]);
                }

                const float* hb = hs + cur * 4096;
#pragma unroll
                for (int k = 0; k < 32; k++) {
                    float4 a4 = *reinterpret_cast<const float4*>(&hb[k * 128 + b0]);
                    float4 w4 = *reinterpret_cast<const float4*>(&ws[(kc + k) * 32 + r0]);
                    float a[4] = {a4.x, a4.y, a4.z, a4.w};
                    float w[4] = {w4.x, w4.y, w4.z, w4.w};
#pragma unroll
                    for (int i = 0; i < 4; i++)
#pragma unroll
                        for (int j = 0; j < 4; j++)
                            acc[i][j] = fmaf(a[i], w[j], acc[i][j]);
                }

                if (more) {
                    float* dst = hs + (cur ^ 1) * 4096;
#pragma unroll
                    for (int i = 0; i < 4; i++) {
                        int kl = lk + i * 4;
                        dst[(kl + 0) * 128 + lb] = pv[i].x;
                        dst[(kl + 1) * 128 + lb] = pv[i].y;
                        dst[(kl + 2) * 128 + lb] = pv[i].z;
                        dst[(kl + 3) * 128 + lb] = pv[i].w;
                    }
                }
                cur ^= 1;
            }
        }

        // ---- exchange partial gates through smem (reuse hs buffer 0) ----
        __syncthreads();
        float* gbuf = hs;
#pragma unroll
        for (int i = 0; i < 4; i++)
#pragma unroll
            for (int j = 0; j < 4; j++)
                gbuf[(r0 + j) * 128 + (b0 + i)] = acc[i][j];
        __syncthreads();

        // ---- LSTM cell update: thread owns (cb, d0+dl0 .. +3), c in regs ----
        {
            const int xv = x[s * NB + cb];
            const float* Grow = &g_G[(size_t)xv * G4];
            float4 Gi = *reinterpret_cast<const float4*>(&Grow[0 * DM + d0 + dl0]);
            float4 Gf = *reinterpret_cast<const float4*>(&Grow[1 * DM + d0 + dl0]);
            float4 Gg = *reinterpret_cast<const float4*>(&Grow[2 * DM + d0 + dl0]);
            float4 Go = *reinterpret_cast<const float4*>(&Grow[3 * DM + d0 + dl0]);
            const float gi[4] = {Gi.x, Gi.y, Gi.z, Gi.w};
            const float gf[4] = {Gf.x, Gf.y, Gf.z, Gf.w};
            const float gg[4] = {Gg.x, Gg.y, Gg.z, Gg.w};
            const float go[4] = {Go.x, Go.y, Go.z, Go.w};

            float hv[4];
#pragma unroll
            for (int t = 0; t < 4; t++) {
                const int dloc = dl0 + t;
                float ai = gbuf[(0  + dloc) * 128 + cb] + gi[t];
                float af = gbuf[(8  + dloc) * 128 + cb] + gf[t];
                float ag = gbuf[(16 + dloc) * 128 + cb] + gg[t];
                float ao = gbuf[(24 + dloc) * 128 + cb] + go[t];

                float iv = 1.f / (1.f + expf(-ai));
                float fv = 1.f / (1.f + expf(-af));
                float gv = tanhf(ag);
                float ov = 1.f / (1.f + expf(-ao));

                float cnew = fv * cr[t] + iv * gv;
                cr[t] = cnew;
                hv[t] = ov * tanhf(cnew);
            }
            float4 hout = make_float4(hv[0], hv[1], hv[2], hv[3]);
            *reinterpret_cast<float4*>(
                &g_hist[(size_t)s * NB * DM + (size_t)cb * DM + d0 + dl0]) = hout;
        }

        // ---- software grid barrier (release h[s] to all CTAs) ----
        __threadfence();
        __syncthreads();
        if (tid == 0) {
            atomicAdd(&g_bar[s], 1);
            while (atomicAdd(&g_bar[s], 0) < NCTA) { }
        }
        __syncthreads();
        __threadfence();
    }
}

// Reset barrier counters so the graph can be replayed deterministically.
__global__ void reset_bar_kernel()
{
    int i = blockIdx.x * blockDim.x + threadIdx.x;
    if (i < NS) g_bar[i] = 0;
}

// =========================================================================
// kernel_launch: G gemm -> persistent LSTM -> barrier reset -> logits gemm
// (4 graph nodes total; no per-step launches)
// =========================================================================
extern "C" void kernel_launch(void* const* d_in, const int* in_sizes, int n_in,
                              void* d_out, int out_size)
{
    const int*   x      = (const int*)  d_in[0];
    const float* emb    = (const float*)d_in[1];
    const float* W_ih   = (const float*)d_in[2];
    const float* W_hh   = (const float*)d_in[3];
    const float* b_ih   = (const float*)d_in[4];
    const float* b_hh   = (const float*)d_in[5];
    const float* W_pred = (const float*)d_in[6];
    const float* b_pred = (const float*)d_in[7];
    float* out = (float*)d_out;

    float* Gp;    cudaGetSymbolAddress((void**)&Gp,    g_G);
    float* histp; cudaGetSymbolAddress((void**)&histp, g_hist);

    // 1) G = emb @ W_ih^T + b_ih + b_hh   (512 x 4096, K=1024)
    {
        dim3 grid(NC / 64, G4 / 64);
        gemm_nt_kernel<0><<<grid, 256>>>(emb, W_ih, b_ih, b_hh, Gp, NC, G4, DM);
    }

    // 2) persistent LSTM over all 1024 steps (single kernel node)
    {
        const int smem_bytes = (32768 + 2 * 4096) * (int)sizeof(float); // 160 KB
        cudaFuncSetAttribute(lstm_persistent_kernel,
                             cudaFuncAttributeMaxDynamicSharedMemorySize, smem_bytes);
        lstm_persistent_kernel<<<NCTA, 256, smem_bytes>>>(x, W_hh);
    }

    // 3) reset barrier counters for the next graph replay
    reset_bar_kernel<<<4, 256>>>();

    // 4) logits = hist @ W_pred^T + b_pred, with [s,b]->[b,s] remap
    {
        dim3 grid((NS * NB) / 64, NC / 64);
        gemm_nt_kernel<1><<<grid, 256>>>(histp, W_pred, b_pred, nullptr, out,
                                         NS * NB, NC, DM);
    }
}

// round 4
// speedup vs baseline: 2.3815x; 2.3815x over previous
#include <cuda_runtime.h>
#include <cuda_fp16.h>
#include <cstdint>
#include <math.h>

typedef unsigned int u32;

// Problem dims
#define DM   1024          // d_model
#define G4   4096          // 4*d_model
#define NB   128           // batch
#define NS   1024          // seq
#define NC   512           // n_classes
#define NCTA 128           // persistent CTAs (one per 8 d-values)

// ---------------- device scratch (static, no allocation) ----------------
__device__ float  g_G[NC * G4];            // 8 MB: G = emb @ W_ih^T + b_ih + b_hh
__device__ float  g_hist[NS * NB * DM];    // 512 MB: all h outputs (fp32, for logits)
__device__ __half g_h16[2][NB * DM];       // fp16 h double-buffer (mma operand)
__device__ int    g_bar[NS];               // grid-barrier counters (reset each launch)

// =========================================================================
// Generic fp32 NT GEMM (known-good): C[M,N] = A @ B^T + bias
// MODE 0: for G.  MODE 1: logits with [s,b]->[b,s] remap.
// =========================================================================
template <int MODE>
__global__ void gemm_nt_kernel(const float* __restrict__ A,
                               const float* __restrict__ Bm,
                               const float* __restrict__ bias0,
                               const float* __restrict__ bias1,
                               float* __restrict__ Cout,
                               int M, int N, int K)
{
    __shared__ float As[16][64];
    __shared__ float Bs[16][64];

    const int tid = threadIdx.x;
    const int tx  = tid & 15;
    const int ty  = tid >> 4;
    const int mBase = blockIdx.x * 64;
    const int nBase = blockIdx.y * 64;

    const int la  = tid >> 2;
    const int lk  = (tid & 3) * 4;

    float acc[4][4];
#pragma unroll
    for (int i = 0; i < 4; i++)
#pragma unroll
        for (int j = 0; j < 4; j++) acc[i][j] = 0.f;

    for (int kc = 0; kc < K; kc += 16) {
        {
            float4 v = *reinterpret_cast<const float4*>(&A[(size_t)(mBase + la) * K + kc + lk]);
            As[lk + 0][la] = v.x; As[lk + 1][la] = v.y;
            As[lk + 2][la] = v.z; As[lk + 3][la] = v.w;
        }
        {
            float4 v = *reinterpret_cast<const float4*>(&Bm[(size_t)(nBase + la) * K + kc + lk]);
            Bs[lk + 0][la] = v.x; Bs[lk + 1][la] = v.y;
            Bs[lk + 2][la] = v.z; Bs[lk + 3][la] = v.w;
        }
        __syncthreads();

#pragma unroll
        for (int k = 0; k < 16; k++) {
            float4 a4 = *reinterpret_cast<const float4*>(&As[k][tx * 4]);
            float4 b4 = *reinterpret_cast<const float4*>(&Bs[k][ty * 4]);
            float a[4] = {a4.x, a4.y, a4.z, a4.w};
            float b[4] = {b4.x, b4.y, b4.z, b4.w};
#pragma unroll
            for (int i = 0; i < 4; i++)
#pragma unroll
                for (int j = 0; j < 4; j++)
                    acc[i][j] = fmaf(a[i], b[j], acc[i][j]);
        }
        __syncthreads();
    }

#pragma unroll
    for (int i = 0; i < 4; i++) {
        int row = mBase + tx * 4 + i;
#pragma unroll
        for (int j = 0; j < 4; j++) {
            int col = nBase + ty * 4 + j;
            if (MODE == 0) {
                Cout[(size_t)row * N + col] = acc[i][j] + bias0[col] + bias1[col];
            } else {
                int s_ = row >> 7;
                int bb = row & 127;
                Cout[(size_t)bb * NS * NC + (size_t)s_ * NC + col] = acc[i][j] + bias0[col];
            }
        }
    }
}

// ---- fast, saturating-safe activations (error ~2^-22 from __expf) ----
__device__ __forceinline__ float fast_sigmoid(float x) {
    return 1.f / (1.f + __expf(-x));
}
__device__ __forceinline__ float fast_tanh(float x) {
    return 1.f - 2.f / (1.f + __expf(2.f * x));   // exact limits at +-inf
}

#define MMA16816(C, A0, A1, A2, A3, B0, B1)                                   \
    asm volatile(                                                             \
        "mma.sync.aligned.m16n8k16.row.col.f32.f16.f16.f32 "                  \
        "{%0,%1,%2,%3}, {%4,%5,%6,%7}, {%8,%9}, {%0,%1,%2,%3};"               \
        : "+f"(C[0]), "+f"(C[1]), "+f"(C[2]), "+f"(C[3])                      \
        : "r"(A0), "r"(A1), "r"(A2), "r"(A3), "r"(B0), "r"(B1))

// =========================================================================
// Persistent tensor-core LSTM: 128 CTAs x 256 threads (8 warps).
// CTA owns 8 d-values (32 gate rows = N). Warp w owns batches [16w,16w+16).
// Per step: acc[4 ntiles] = h_prev(fp16, ldcg) @ Wfrag(fp16 smem), then the
// LSTM cell update is PER-THREAD (i/f/g/o for same (b,d) land in one thread),
// c-state in registers, h written fp32 (hist) + fp16 (double buffer).
// =========================================================================
__global__ void __launch_bounds__(256, 1)
lstm_mma_kernel(const int* __restrict__ x,
                const float* __restrict__ Whh)
{
    extern __shared__ uint4 wfrag[];   // [64 iters][2 nt-pairs][32 lanes] uint4

    const int tid  = threadIdx.x;
    const int lane = tid & 31;
    const int w    = tid >> 5;
    const int d0   = blockIdx.x * 8;
    const int tig  = lane & 3;         // thread-in-group
    const int grp  = lane >> 2;        // group id (0..7)

    // ---- one-time: W slice -> fp16 B-fragment order in smem ----
    for (int e = tid; e < 64 * 2 * 32; e += 256) {
        int l   = e & 31;
        int nth = (e >> 5) & 1;
        int it  = e >> 6;
        int k0  = it * 16 + 2 * (l & 3);
        u32 v[4];
#pragma unroll
        for (int h = 0; h < 2; h++) {
            int nt   = 2 * nth + h;
            int grow = nt * DM + d0 + (l >> 2);      // gate-major global W row
            const float* Wr = &Whh[(size_t)grow * DM];
            __half2 p0 = __floats2half2_rn(Wr[k0],     Wr[k0 + 1]);
            __half2 p1 = __floats2half2_rn(Wr[k0 + 8], Wr[k0 + 9]);
            v[h * 2 + 0] = *reinterpret_cast<u32*>(&p0);
            v[h * 2 + 1] = *reinterpret_cast<u32*>(&p1);
        }
        wfrag[e] = make_uint4(v[0], v[1], v[2], v[3]);
    }
    __syncthreads();

    // ---- persistent per-thread state ----
    const int b_lo = w * 16 + grp;
    const int b_hi = b_lo + 8;
    const int dd   = d0 + 2 * tig;     // this thread's d pair (dd, dd+1)
    float cr[4] = {0.f, 0.f, 0.f, 0.f};   // c state: [p(b_lo/b_hi)][e(d/d+1)]

    for (int s = 0; s < NS; s++) {
        float acc[4][4];               // [ntile = gate][c0..c3]
#pragma unroll
        for (int i = 0; i < 4; i++)
#pragma unroll
            for (int j = 0; j < 4; j++) acc[i][j] = 0.f;

        if (s > 0) {
            // h_prev as u32 (fp16x2) rows; L2-only loads (L1 would go stale)
            const u32* hp = reinterpret_cast<const u32*>(&g_h16[(s - 1) & 1][0]);
            const u32* rowLo = hp + (size_t)b_lo * (DM / 2);
            const u32* rowHi = hp + (size_t)b_hi * (DM / 2);

#pragma unroll 4
            for (int it = 0; it < 64; it++) {
                uint4 w01 = wfrag[(it * 2 + 0) * 32 + lane];
                uint4 w23 = wfrag[(it * 2 + 1) * 32 + lane];
                u32 a0 = __ldcg(rowLo + it * 8 + tig);
                u32 a1 = __ldcg(rowHi + it * 8 + tig);
                u32 a2 = __ldcg(rowLo + it * 8 + tig + 4);
                u32 a3 = __ldcg(rowHi + it * 8 + tig + 4);
                MMA16816(acc[0], a0, a1, a2, a3, w01.x, w01.y);
                MMA16816(acc[1], a0, a1, a2, a3, w01.z, w01.w);
                MMA16816(acc[2], a0, a1, a2, a3, w23.x, w23.y);
                MMA16816(acc[3], a0, a1, a2, a3, w23.z, w23.w);
            }
        }

        // ---- per-thread LSTM cell update for (b_lo,dd..dd+1),(b_hi,dd..dd+1) ----
        {
            const int xlo = x[s * NB + b_lo];
            const int xhi = x[s * NB + b_hi];
            const float* Gp[2] = { &g_G[(size_t)xlo * G4 + dd],
                                   &g_G[(size_t)xhi * G4 + dd] };
            const int bb[2] = { b_lo, b_hi };

#pragma unroll
            for (int p = 0; p < 2; p++) {
                float2 gi = *reinterpret_cast<const float2*>(Gp[p] + 0 * DM);
                float2 gf = *reinterpret_cast<const float2*>(Gp[p] + 1 * DM);
                float2 gg = *reinterpret_cast<const float2*>(Gp[p] + 2 * DM);
                float2 go = *reinterpret_cast<const float2*>(Gp[p] + 3 * DM);

                float hv[2];
#pragma unroll
                for (int e = 0; e < 2; e++) {
                    float ai = acc[0][p * 2 + e] + (e ? gi.y : gi.x);
                    float af = acc[1][p * 2 + e] + (e ? gf.y : gf.x);
                    float ag = acc[2][p * 2 + e] + (e ? gg.y : gg.x);
                    float ao = acc[3][p * 2 + e] + (e ? go.y : go.x);

                    float iv = fast_sigmoid(ai);
                    float fv = fast_sigmoid(af);
                    float gv = fast_tanh(ag);
                    float ov = fast_sigmoid(ao);

                    float cnew = fmaf(fv, cr[p * 2 + e], iv * gv);
                    cr[p * 2 + e] = cnew;
                    hv[e] = ov * fast_tanh(cnew);
                }
                // fp32 h for logits
                *reinterpret_cast<float2*>(
                    &g_hist[(size_t)s * NB * DM + (size_t)bb[p] * DM + dd]) =
                    make_float2(hv[0], hv[1]);
                // fp16 h for next-step mma
                __half2 hh = __floats2half2_rn(hv[0], hv[1]);
                *reinterpret_cast<u32*>(&g_h16[s & 1][bb[p] * DM + dd]) =
                    *reinterpret_cast<u32*>(&hh);
            }
        }

        // ---- software grid barrier (release h[s] to all CTAs) ----
        __syncthreads();
        __threadfence();
        if (tid == 0) {
            atomicAdd(&g_bar[s], 1);
            volatile int* bp = &g_bar[s];
            while (*bp < NCTA) { }
        }
        __syncthreads();
        __threadfence();
    }
}

// Reset barrier counters so the graph replays deterministically.
__global__ void reset_bar_kernel()
{
    int i = blockIdx.x * blockDim.x + threadIdx.x;
    if (i < NS) g_bar[i] = 0;
}

// =========================================================================
// kernel_launch: G gemm -> persistent mma LSTM -> bar reset -> logits gemm
// =========================================================================
extern "C" void kernel_launch(void* const* d_in, const int* in_sizes, int n_in,
                              void* d_out, int out_size)
{
    const int*   x      = (const int*)  d_in[0];
    const float* emb    = (const float*)d_in[1];
    const float* W_ih   = (const float*)d_in[2];
    const float* W_hh   = (const float*)d_in[3];
    const float* b_ih   = (const float*)d_in[4];
    const float* b_hh   = (const float*)d_in[5];
    const float* W_pred = (const float*)d_in[6];
    const float* b_pred = (const float*)d_in[7];
    float* out = (float*)d_out;

    float* Gp;    cudaGetSymbolAddress((void**)&Gp,    g_G);
    float* histp; cudaGetSymbolAddress((void**)&histp, g_hist);

    // 1) G = emb @ W_ih^T + b_ih + b_hh   (512 x 4096, K=1024)
    {
        dim3 grid(NC / 64, G4 / 64);
        gemm_nt_kernel<0><<<grid, 256>>>(emb, W_ih, b_ih, b_hh, Gp, NC, G4, DM);
    }

    // 2) persistent tensor-core LSTM (single node)
    {
        const int smem_bytes = 64 * 2 * 32 * (int)sizeof(uint4);  // 64 KB
        cudaFuncSetAttribute(lstm_mma_kernel,
                             cudaFuncAttributeMaxDynamicSharedMemorySize, smem_bytes);
        lstm_mma_kernel<<<NCTA, 256, smem_bytes>>>(x, W_hh);
    }

    // 3) reset barrier counters for the next graph replay
    reset_bar_kernel<<<4, 256>>>();

    // 4) logits = hist @ W_pred^T + b_pred (fp32, known-good)
    {
        dim3 grid((NS * NB) / 64, NC / 64);
        gemm_nt_kernel<1><<<grid, 256>>>(histp, W_pred, b_pred, nullptr, out,
                                         NS * NB, NC, DM);
    }
}

// round 5
// speedup vs baseline: 3.9103x; 1.6419x over previous
#include <cuda_runtime.h>
#include <cuda_fp16.h>
#include <cstdint>
#include <math.h>

typedef unsigned int u32;

// Problem dims
#define DM   1024          // d_model
#define G4   4096          // 4*d_model
#define NB   128           // batch
#define NS   1024          // seq
#define NC   512           // n_classes
#define NCTA 128           // persistent CTAs (one per 8 d-values)

// PH layout: per step, 64 batch-pairs x 512 k2-slots x uint2 {h2[b], h2[b+8]}
// = 65536 u32 = 256 KB / step. Slot permutation makes one uint4 load at
// (pair*1024 + it*16 + 4*tig) yield the full m16n8k16 A-fragment.
#define PH_STEP 65536

// ---------------- device scratch (static, no allocation) ----------------
__device__ float g_G[NC * G4];            // 8 MB: G = emb @ W_ih^T + b_ih + b_hh
__device__ u32   g_PH[NS * PH_STEP];      // 256 MB: fp16 h history, fragment-packed
__device__ uint4 g_WpPack[8 * 64 * 4 * 32]; // 1 MB: W_pred fp16 in B-fragment order
__device__ int   g_bar[NS * 256];         // 8 spread counters/step (stride 32 ints)

// =========================================================================
// fp32 NT GEMM (known-good) for G: C[M,N] = A @ B^T + bias0 + bias1
// =========================================================================
__global__ void gemm_nt_kernel(const float* __restrict__ A,
                               const float* __restrict__ Bm,
                               const float* __restrict__ bias0,
                               const float* __restrict__ bias1,
                               float* __restrict__ Cout,
                               int M, int N, int K)
{
    __shared__ float As[16][64];
    __shared__ float Bs[16][64];

    const int tid = threadIdx.x;
    const int tx  = tid & 15;
    const int ty  = tid >> 4;
    const int mBase = blockIdx.x * 64;
    const int nBase = blockIdx.y * 64;

    const int la  = tid >> 2;
    const int lk  = (tid & 3) * 4;

    float acc[4][4];
#pragma unroll
    for (int i = 0; i < 4; i++)
#pragma unroll
        for (int j = 0; j < 4; j++) acc[i][j] = 0.f;

    for (int kc = 0; kc < K; kc += 16) {
        {
            float4 v = *reinterpret_cast<const float4*>(&A[(size_t)(mBase + la) * K + kc + lk]);
            As[lk + 0][la] = v.x; As[lk + 1][la] = v.y;
            As[lk + 2][la] = v.z; As[lk + 3][la] = v.w;
        }
        {
            float4 v = *reinterpret_cast<const float4*>(&Bm[(size_t)(nBase + la) * K + kc + lk]);
            Bs[lk + 0][la] = v.x; Bs[lk + 1][la] = v.y;
            Bs[lk + 2][la] = v.z; Bs[lk + 3][la] = v.w;
        }
        __syncthreads();

#pragma unroll
        for (int k = 0; k < 16; k++) {
            float4 a4 = *reinterpret_cast<const float4*>(&As[k][tx * 4]);
            float4 b4 = *reinterpret_cast<const float4*>(&Bs[k][ty * 4]);
            float a[4] = {a4.x, a4.y, a4.z, a4.w};
            float b[4] = {b4.x, b4.y, b4.z, b4.w};
#pragma unroll
            for (int i = 0; i < 4; i++)
#pragma unroll
                for (int j = 0; j < 4; j++)
                    acc[i][j] = fmaf(a[i], b[j], acc[i][j]);
        }
        __syncthreads();
    }

#pragma unroll
    for (int i = 0; i < 4; i++) {
        int row = mBase + tx * 4 + i;
#pragma unroll
        for (int j = 0; j < 4; j++) {
            int col = nBase + ty * 4 + j;
            Cout[(size_t)row * N + col] = acc[i][j] + bias0[col] + bias1[col];
        }
    }
}

// ---- fast, saturating-safe activations ----
__device__ __forceinline__ float fast_sigmoid(float x) {
    return 1.f / (1.f + __expf(-x));
}
__device__ __forceinline__ float fast_tanh(float x) {
    return 1.f - 2.f / (1.f + __expf(2.f * x));
}

#define MMA16816(C, A0, A1, A2, A3, B0, B1)                                   \
    asm volatile(                                                             \
        "mma.sync.aligned.m16n8k16.row.col.f32.f16.f16.f32 "                  \
        "{%0,%1,%2,%3}, {%4,%5,%6,%7}, {%8,%9}, {%0,%1,%2,%3};"               \
        : "+f"(C[0]), "+f"(C[1]), "+f"(C[2]), "+f"(C[3])                      \
        : "r"(A0), "r"(A1), "r"(A2), "r"(A3), "r"(B0), "r"(B1))

// =========================================================================
// Pack W_pred (fp32) -> g_WpPack (fp16, B-fragment order).
// idx = (nb<<13) | (it<<7) | (q<<5) | lane, uint4 = {b0(t=2q),b1(2q),b0(2q+1),b1(2q+1)}
// =========================================================================
__global__ void pack_wpred_kernel(const float* __restrict__ Wp)
{
    int idx  = blockIdx.x * 256 + threadIdx.x;     // 0..65535
    int lane = idx & 31;
    int q    = (idx >> 5) & 3;
    int it   = (idx >> 7) & 63;
    int nb   = idx >> 13;

    u32 v[4];
#pragma unroll
    for (int h = 0; h < 2; h++) {
        int t = 2 * q + h;
        int n = nb * 64 + t * 8 + (lane >> 2);
        const float* row = Wp + (size_t)n * DM;
        int j0 = it * 8 + (lane & 3);
        int j1 = j0 + 4;
        __half2 p0 = __floats2half2_rn(row[2 * j0], row[2 * j0 + 1]);
        __half2 p1 = __floats2half2_rn(row[2 * j1], row[2 * j1 + 1]);
        v[2 * h + 0] = *reinterpret_cast<u32*>(&p0);
        v[2 * h + 1] = *reinterpret_cast<u32*>(&p1);
    }
    g_WpPack[idx] = make_uint4(v[0], v[1], v[2], v[3]);
}

// =========================================================================
// Persistent tensor-core LSTM: 128 CTAs x 256 threads (8 warps).
// A-fragments: ONE LDG.128 per iter from fragment-packed g_PH[s-1].
// W fragments resident in smem. Thread-local cell update, c in registers.
// h stored fragment-packed to g_PH[s] (uint2 per thread).
// =========================================================================
__global__ void __launch_bounds__(256, 1)
lstm_mma_kernel(const int* __restrict__ x,
                const float* __restrict__ Whh)
{
    extern __shared__ uint4 wfrag[];   // [64 iters][2 nt-pairs][32 lanes] uint4

    const int tid  = threadIdx.x;
    const int lane = tid & 31;
    const int w    = tid >> 5;
    const int d0   = blockIdx.x * 8;
    const int tig  = lane & 3;
    const int grp  = lane >> 2;

    // ---- one-time: W_hh slice -> fp16 B-fragment order in smem ----
    for (int e = tid; e < 64 * 2 * 32; e += 256) {
        int l   = e & 31;
        int nth = (e >> 5) & 1;
        int it  = e >> 6;
        int k0  = it * 16 + 2 * (l & 3);
        u32 v[4];
#pragma unroll
        for (int h = 0; h < 2; h++) {
            int nt   = 2 * nth + h;                  // gate index 0..3
            int grow = nt * DM + d0 + (l >> 2);      // gate-major W_hh row
            const float* Wr = &Whh[(size_t)grow * DM];
            __half2 p0 = __floats2half2_rn(Wr[k0],     Wr[k0 + 1]);
            __half2 p1 = __floats2half2_rn(Wr[k0 + 8], Wr[k0 + 9]);
            v[h * 2 + 0] = *reinterpret_cast<u32*>(&p0);
            v[h * 2 + 1] = *reinterpret_cast<u32*>(&p1);
        }
        wfrag[e] = make_uint4(v[0], v[1], v[2], v[3]);
    }
    __syncthreads();

    // ---- persistent per-thread state ----
    const int pair = w * 8 + grp;          // batch-pair id (b_lo = w*16+grp)
    const int b_lo = w * 16 + grp;
    const int b_hi = b_lo + 8;
    const int dd   = d0 + 2 * tig;         // this thread's d pair
    // PH write slot for k2 = dd/2
    const int k2   = (d0 >> 1) + tig;
    const int p8   = k2 & 7;
    const int slot = (p8 < 4) ? (2 * p8) : (2 * (p8 - 4) + 1);
    const int wIdx = pair * 1024 + ((k2 >> 3) * 8 + slot) * 2;   // u32 index
    const int aBase = pair * 1024 + 4 * tig;                      // u32 index

    float cr[4] = {0.f, 0.f, 0.f, 0.f};

    for (int s = 0; s < NS; s++) {
        float acc[4][4];
#pragma unroll
        for (int i = 0; i < 4; i++)
#pragma unroll
            for (int j = 0; j < 4; j++) acc[i][j] = 0.f;

        if (s > 0) {
            const u32* ph = g_PH + (size_t)(s - 1) * PH_STEP;
#pragma unroll 4
            for (int it = 0; it < 64; it++) {
                uint4 w01 = wfrag[(it * 2 + 0) * 32 + lane];
                uint4 w23 = wfrag[(it * 2 + 1) * 32 + lane];
                uint4 a = *reinterpret_cast<const uint4*>(ph + aBase + it * 16);
                MMA16816(acc[0], a.x, a.y, a.z, a.w, w01.x, w01.y);
                MMA16816(acc[1], a.x, a.y, a.z, a.w, w01.z, w01.w);
                MMA16816(acc[2], a.x, a.y, a.z, a.w, w23.x, w23.y);
                MMA16816(acc[3], a.x, a.y, a.z, a.w, w23.z, w23.w);
            }
        }

        // ---- thread-local LSTM cell update ----
        {
            const int xlo = x[s * NB + b_lo];
            const int xhi = x[s * NB + b_hi];
            const float* Gp[2] = { &g_G[(size_t)xlo * G4 + dd],
                                   &g_G[(size_t)xhi * G4 + dd] };
            u32 h2out[2];

#pragma unroll
            for (int p = 0; p < 2; p++) {
                float2 gi = *reinterpret_cast<const float2*>(Gp[p] + 0 * DM);
                float2 gf = *reinterpret_cast<const float2*>(Gp[p] + 1 * DM);
                float2 gg = *reinterpret_cast<const float2*>(Gp[p] + 2 * DM);
                float2 go = *reinterpret_cast<const float2*>(Gp[p] + 3 * DM);

                float hv[2];
#pragma unroll
                for (int e = 0; e < 2; e++) {
                    float ai = acc[0][p * 2 + e] + (e ? gi.y : gi.x);
                    float af = acc[1][p * 2 + e] + (e ? gf.y : gf.x);
                    float ag = acc[2][p * 2 + e] + (e ? gg.y : gg.x);
                    float ao = acc[3][p * 2 + e] + (e ? go.y : go.x);

                    float iv = fast_sigmoid(ai);
                    float fv = fast_sigmoid(af);
                    float gv = fast_tanh(ag);
                    float ov = fast_sigmoid(ao);

                    float cnew = fmaf(fv, cr[p * 2 + e], iv * gv);
                    cr[p * 2 + e] = cnew;
                    hv[e] = ov * fast_tanh(cnew);
                }
                __half2 hh = __floats2half2_rn(hv[0], hv[1]);
                h2out[p] = *reinterpret_cast<u32*>(&hh);
            }
            // fragment-packed store: {h2[b_lo], h2[b_hi]} as uint2
            *reinterpret_cast<uint2*>(g_PH + (size_t)s * PH_STEP + wIdx) =
                make_uint2(h2out[0], h2out[1]);
        }

        // ---- grid barrier: 8 spread counters, lane-parallel poll ----
        __syncthreads();
        __threadfence();
        if (w == 0) {
            if (lane == 0)
                atomicAdd(&g_bar[s * 256 + (blockIdx.x & 7) * 32], 1);
            int done;
            do {
                int v = (lane < 8)
                      ? *((volatile int*)&g_bar[s * 256 + lane * 32]) : 16;
                done = __all_sync(0xffffffffu, v >= 16);
            } while (!done);
        }
        __syncthreads();
        __threadfence();
    }
}

// Reset barrier counters for deterministic graph replay.
__global__ void reset_bar_kernel()
{
    g_bar[blockIdx.x * 256 + threadIdx.x] = 0;
}

// =========================================================================
// Logits: out[b][s][n] = h(fp16 PH) @ W_pred^T + b_pred via mma.
// Grid (8 n-groups, 1024 s). CTA: stage its 128 KB W-fragment pack to smem,
// then 64 k-iters of 1 LDG.128 (A) + 4 LDS.128 (B) + 8 HMMA per lane.
// =========================================================================
__global__ void __launch_bounds__(256, 1)
logits_mma_kernel(const float* __restrict__ bias, float* __restrict__ out)
{
    extern __shared__ uint4 wb[];      // 8192 uint4 = 128 KB

    const int tid  = threadIdx.x;
    const int lane = tid & 31;
    const int w    = tid >> 5;
    const int nb   = blockIdx.x;
    const int s    = blockIdx.y;
    const int grp  = lane >> 2;
    const int tig  = lane & 3;

    for (int i = tid; i < 8192; i += 256)
        wb[i] = g_WpPack[nb * 8192 + i];
    __syncthreads();

    const u32* ph   = g_PH + (size_t)s * PH_STEP;
    const int aBase = (w * 8 + grp) * 1024 + 4 * tig;

    float acc[8][4];
#pragma unroll
    for (int t = 0; t < 8; t++)
#pragma unroll
        for (int j = 0; j < 4; j++) acc[t][j] = 0.f;

#pragma unroll 2
    for (int it = 0; it < 64; it++) {
        uint4 a = *reinterpret_cast<const uint4*>(ph + aBase + it * 16);
#pragma unroll
        for (int q = 0; q < 4; q++) {
            uint4 wq = wb[it * 128 + q * 32 + lane];
            MMA16816(acc[2 * q],     a.x, a.y, a.z, a.w, wq.x, wq.y);
            MMA16816(acc[2 * q + 1], a.x, a.y, a.z, a.w, wq.z, wq.w);
        }
    }

    const int bL = w * 16 + grp;
    const int bH = bL + 8;
#pragma unroll
    for (int t = 0; t < 8; t++) {
        int col = nb * 64 + t * 8 + 2 * tig;
        float2 bz = *reinterpret_cast<const float2*>(bias + col);
        *reinterpret_cast<float2*>(out + (size_t)bL * NS * NC + (size_t)s * NC + col) =
            make_float2(acc[t][0] + bz.x, acc[t][1] + bz.y);
        *reinterpret_cast<float2*>(out + (size_t)bH * NS * NC + (size_t)s * NC + col) =
            make_float2(acc[t][2] + bz.x, acc[t][3] + bz.y);
    }
}

// =========================================================================
// kernel_launch: G gemm -> pack W_pred -> LSTM -> bar reset -> logits mma
// =========================================================================
extern "C" void kernel_launch(void* const* d_in, const int* in_sizes, int n_in,
                              void* d_out, int out_size)
{
    const int*   x      = (const int*)  d_in[0];
    const float* emb    = (const float*)d_in[1];
    const float* W_ih   = (const float*)d_in[2];
    const float* W_hh   = (const float*)d_in[3];
    const float* b_ih   = (const float*)d_in[4];
    const float* b_hh   = (const float*)d_in[5];
    const float* W_pred = (const float*)d_in[6];
    const float* b_pred = (const float*)d_in[7];
    float* out = (float*)d_out;

    float* Gp; cudaGetSymbolAddress((void**)&Gp, g_G);

    // 1) G = emb @ W_ih^T + b_ih + b_hh   (512 x 4096, K=1024)
    {
        dim3 grid(NC / 64, G4 / 64);
        gemm_nt_kernel<<<grid, 256>>>(emb, W_ih, b_ih, b_hh, Gp, NC, G4, DM);
    }

    // 2) pack W_pred into fp16 B-fragment order
    pack_wpred_kernel<<<256, 256>>>(W_pred);

    // 3) persistent tensor-core LSTM (single node)
    {
        const int smem_bytes = 64 * 2 * 32 * (int)sizeof(uint4);  // 64 KB
        cudaFuncSetAttribute(lstm_mma_kernel,
                             cudaFuncAttributeMaxDynamicSharedMemorySize, smem_bytes);
        lstm_mma_kernel<<<NCTA, 256, smem_bytes>>>(x, W_hh);
    }

    // 4) reset barrier counters for the next graph replay
    reset_bar_kernel<<<NS, 256>>>();

    // 5) logits via tensor cores
    {
        const int smem_bytes = 8192 * (int)sizeof(uint4);         // 128 KB
        cudaFuncSetAttribute(logits_mma_kernel,
                             cudaFuncAttributeMaxDynamicSharedMemorySize, smem_bytes);
        dim3 grid(8, NS);
        logits_mma_kernel<<<grid, 256, smem_bytes>>>(b_pred, out);
    }
}

// round 6
// speedup vs baseline: 4.5956x; 1.1753x over previous
#include <cuda_runtime.h>
#include <cuda_fp16.h>
#include <cstdint>
#include <math.h>

typedef unsigned int u32;

// Problem dims
#define DM   1024          // d_model
#define G4   4096          // 4*d_model
#define NB   128           // batch
#define NS   1024          // seq
#define NC   512           // n_classes
#define NCTA 128           // persistent CTAs (one per 8 d-values)

// PH layout: per step, 64 batch-pairs x 512 k2-slots x uint2 {h2[b], h2[b+8]}
// = 65536 u32 = 256 KB / step. Slot permutation makes one uint4 load at
// (pair*1024 + it*16 + 4*tig) yield the full m16n8k16 A-fragment.
#define PH_STEP 65536

// ---------------- device scratch (static, no allocation) ----------------
__device__ float g_G[NC * G4];              // 8 MB
__device__ u32   g_PH[NS * PH_STEP];        // 256 MB fp16 h history, fragment-packed
__device__ uint4 g_WpPack[8 * 64 * 4 * 32]; // 1 MB W_pred fp16 B-fragment order
__device__ int   g_bar[NS * 256];           // 8 spread counters/step (stride 32)

// =========================================================================
// fp32 NT GEMM for G: C[M,N] = A @ B^T + bias0 + bias1  (known-good)
// =========================================================================
__global__ void gemm_nt_kernel(const float* __restrict__ A,
                               const float* __restrict__ Bm,
                               const float* __restrict__ bias0,
                               const float* __restrict__ bias1,
                               float* __restrict__ Cout,
                               int M, int N, int K)
{
    __shared__ float As[16][64];
    __shared__ float Bs[16][64];

    const int tid = threadIdx.x;
    const int tx  = tid & 15;
    const int ty  = tid >> 4;
    const int mBase = blockIdx.x * 64;
    const int nBase = blockIdx.y * 64;

    const int la  = tid >> 2;
    const int lk  = (tid & 3) * 4;

    float acc[4][4];
#pragma unroll
    for (int i = 0; i < 4; i++)
#pragma unroll
        for (int j = 0; j < 4; j++) acc[i][j] = 0.f;

    for (int kc = 0; kc < K; kc += 16) {
        {
            float4 v = *reinterpret_cast<const float4*>(&A[(size_t)(mBase + la) * K + kc + lk]);
            As[lk + 0][la] = v.x; As[lk + 1][la] = v.y;
            As[lk + 2][la] = v.z; As[lk + 3][la] = v.w;
        }
        {
            float4 v = *reinterpret_cast<const float4*>(&Bm[(size_t)(nBase + la) * K + kc + lk]);
            Bs[lk + 0][la] = v.x; Bs[lk + 1][la] = v.y;
            Bs[lk + 2][la] = v.z; Bs[lk + 3][la] = v.w;
        }
        __syncthreads();

#pragma unroll
        for (int k = 0; k < 16; k++) {
            float4 a4 = *reinterpret_cast<const float4*>(&As[k][tx * 4]);
            float4 b4 = *reinterpret_cast<const float4*>(&Bs[k][ty * 4]);
            float a[4] = {a4.x, a4.y, a4.z, a4.w};
            float b[4] = {b4.x, b4.y, b4.z, b4.w};
#pragma unroll
            for (int i = 0; i < 4; i++)
#pragma unroll
                for (int j = 0; j < 4; j++)
                    acc[i][j] = fmaf(a[i], b[j], acc[i][j]);
        }
        __syncthreads();
    }

#pragma unroll
    for (int i = 0; i < 4; i++) {
        int row = mBase + tx * 4 + i;
#pragma unroll
        for (int j = 0; j < 4; j++) {
            int col = nBase + ty * 4 + j;
            Cout[(size_t)row * N + col] = acc[i][j] + bias0[col] + bias1[col];
        }
    }
}

// ---- fast, saturating-safe activations ----
__device__ __forceinline__ float fast_sigmoid(float x) {
    return 1.f / (1.f + __expf(-x));
}
__device__ __forceinline__ float fast_tanh(float x) {
    return 1.f - 2.f / (1.f + __expf(2.f * x));
}

#define MMA16816(C, A0, A1, A2, A3, B0, B1)                                   \
    asm volatile(                                                             \
        "mma.sync.aligned.m16n8k16.row.col.f32.f16.f16.f32 "                  \
        "{%0,%1,%2,%3}, {%4,%5,%6,%7}, {%8,%9}, {%0,%1,%2,%3};"               \
        : "+f"(C[0]), "+f"(C[1]), "+f"(C[2]), "+f"(C[3])                      \
        : "r"(A0), "r"(A1), "r"(A2), "r"(A3), "r"(B0), "r"(B1))

// =========================================================================
// Pack W_pred (fp32) -> g_WpPack (fp16, B-fragment order).
// =========================================================================
__global__ void pack_wpred_kernel(const float* __restrict__ Wp)
{
    int idx  = blockIdx.x * 256 + threadIdx.x;     // 0..65535
    int lane = idx & 31;
    int q    = (idx >> 5) & 3;
    int it   = (idx >> 7) & 63;
    int nb   = idx >> 13;

    u32 v[4];
#pragma unroll
    for (int h = 0; h < 2; h++) {
        int t = 2 * q + h;
        int n = nb * 64 + t * 8 + (lane >> 2);
        const float* row = Wp + (size_t)n * DM;
        int j0 = it * 8 + (lane & 3);
        int j1 = j0 + 4;
        __half2 p0 = __floats2half2_rn(row[2 * j0], row[2 * j0 + 1]);
        __half2 p1 = __floats2half2_rn(row[2 * j1], row[2 * j1 + 1]);
        v[2 * h + 0] = *reinterpret_cast<u32*>(&p0);
        v[2 * h + 1] = *reinterpret_cast<u32*>(&p1);
    }
    g_WpPack[idx] = make_uint4(v[0], v[1], v[2], v[3]);
}

// =========================================================================
// Persistent tensor-core LSTM: 128 CTAs x 512 threads (16 warps).
// Warp w (0..7): batches [16w,16w+16), K in [0,512).
// Warp w (8..15): same batches as w-8, K in [512,1024); split-K reduced in smem.
// A-fragments: 1 LDG.128/iter from fragment-packed g_PH[s-1]. W in smem.
// Thread-local cell update (warps 0..7), c in registers, G gather hoisted
// above the mma loop.
// =========================================================================
__global__ void __launch_bounds__(512, 1)
lstm_mma_kernel(const int* __restrict__ x,
                const float* __restrict__ Whh)
{
    extern __shared__ char smem_raw[];
    uint4* wfrag = reinterpret_cast<uint4*>(smem_raw);            // 4096 uint4 = 64 KB
    float* red   = reinterpret_cast<float*>(smem_raw + 65536);    // 4096 f  = 16 KB

    const int tid  = threadIdx.x;
    const int lane = tid & 31;
    const int w    = tid >> 5;          // 0..15
    const int bg   = w & 7;             // batch group
    const int kh   = w >> 3;            // K half
    const int d0   = blockIdx.x * 8;
    const int tig  = lane & 3;
    const int grp  = lane >> 2;

    // ---- one-time: W_hh slice -> fp16 B-fragment order in smem ----
    for (int e = tid; e < 64 * 2 * 32; e += 512) {
        int l   = e & 31;
        int nth = (e >> 5) & 1;
        int it  = e >> 6;
        int k0  = it * 16 + 2 * (l & 3);
        u32 v[4];
#pragma unroll
        for (int h = 0; h < 2; h++) {
            int nt   = 2 * nth + h;                  // gate index 0..3
            int grow = nt * DM + d0 + (l >> 2);      // gate-major W_hh row
            const float* Wr = &Whh[(size_t)grow * DM];
            __half2 p0 = __floats2half2_rn(Wr[k0],     Wr[k0 + 1]);
            __half2 p1 = __floats2half2_rn(Wr[k0 + 8], Wr[k0 + 9]);
            v[h * 2 + 0] = *reinterpret_cast<u32*>(&p0);
            v[h * 2 + 1] = *reinterpret_cast<u32*>(&p1);
        }
        wfrag[e] = make_uint4(v[0], v[1], v[2], v[3]);
    }
    __syncthreads();

    // ---- persistent per-thread state ----
    const int pair = bg * 8 + grp;
    const int b_lo = bg * 16 + grp;
    const int b_hi = b_lo + 8;
    const int dd   = d0 + 2 * tig;
    // PH write slot for k2 = dd/2 (warps 0..7 only)
    const int k2   = (d0 >> 1) + tig;
    const int p8   = k2 & 7;
    const int slot = (p8 < 4) ? (2 * p8) : (2 * (p8 - 4) + 1);
    const int wIdx  = pair * 1024 + ((k2 >> 3) * 8 + slot) * 2;
    const int aBase = pair * 1024 + 4 * tig;
    const int rIdx  = (bg * 32 + lane) * 16;   // split-K exchange slot

    float cr[4] = {0.f, 0.f, 0.f, 0.f};

    for (int s = 0; s < NS; s++) {
        float acc[4][4];
#pragma unroll
        for (int i = 0; i < 4; i++)
#pragma unroll
            for (int j = 0; j < 4; j++) acc[i][j] = 0.f;

        // ---- hoisted gather: x and G rows (depend only on s) ----
        float gi[2][2], gf[2][2], gg[2][2], go[2][2];
        if (kh == 0) {
            const int xlo = __ldg(&x[s * NB + b_lo]);
            const int xhi = __ldg(&x[s * NB + b_hi]);
            const float* GpL = &g_G[(size_t)xlo * G4 + dd];
            const float* GpH = &g_G[(size_t)xhi * G4 + dd];
#pragma unroll
            for (int p = 0; p < 2; p++) {
                const float* Gp = p ? GpH : GpL;
                float2 a0 = *reinterpret_cast<const float2*>(Gp + 0 * DM);
                float2 a1 = *reinterpret_cast<const float2*>(Gp + 1 * DM);
                float2 a2 = *reinterpret_cast<const float2*>(Gp + 2 * DM);
                float2 a3 = *reinterpret_cast<const float2*>(Gp + 3 * DM);
                gi[p][0] = a0.x; gi[p][1] = a0.y;
                gf[p][0] = a1.x; gf[p][1] = a1.y;
                gg[p][0] = a2.x; gg[p][1] = a2.y;
                go[p][0] = a3.x; go[p][1] = a3.y;
            }
        }

        if (s > 0) {
            const u32* ph = g_PH + (size_t)(s - 1) * PH_STEP;
            const int it0 = kh * 32;
#pragma unroll 4
            for (int i = 0; i < 32; i++) {
                const int it = it0 + i;
                uint4 w01 = wfrag[(it * 2 + 0) * 32 + lane];
                uint4 w23 = wfrag[(it * 2 + 1) * 32 + lane];
                uint4 a = *reinterpret_cast<const uint4*>(ph + aBase + it * 16);
                MMA16816(acc[0], a.x, a.y, a.z, a.w, w01.x, w01.y);
                MMA16816(acc[1], a.x, a.y, a.z, a.w, w01.z, w01.w);
                MMA16816(acc[2], a.x, a.y, a.z, a.w, w23.x, w23.y);
                MMA16816(acc[3], a.x, a.y, a.z, a.w, w23.z, w23.w);
            }
        }

        // ---- split-K reduction: warps 8..15 publish, warps 0..7 add ----
        if (kh == 1) {
            float* r = red + rIdx;
#pragma unroll
            for (int t = 0; t < 4; t++)
                *reinterpret_cast<float4*>(r + t * 4) =
                    make_float4(acc[t][0], acc[t][1], acc[t][2], acc[t][3]);
        }
        __syncthreads();

        if (kh == 0) {
            const float* r = red + rIdx;
#pragma unroll
            for (int t = 0; t < 4; t++) {
                float4 v = *reinterpret_cast<const float4*>(r + t * 4);
                acc[t][0] += v.x; acc[t][1] += v.y;
                acc[t][2] += v.z; acc[t][3] += v.w;
            }

            // ---- thread-local LSTM cell update ----
            u32 h2out[2];
#pragma unroll
            for (int p = 0; p < 2; p++) {
                float hv[2];
#pragma unroll
                for (int e = 0; e < 2; e++) {
                    float ai = acc[0][p * 2 + e] + gi[p][e];
                    float af = acc[1][p * 2 + e] + gf[p][e];
                    float ag = acc[2][p * 2 + e] + gg[p][e];
                    float ao = acc[3][p * 2 + e] + go[p][e];

                    float iv = fast_sigmoid(ai);
                    float fv = fast_sigmoid(af);
                    float gv = fast_tanh(ag);
                    float ov = fast_sigmoid(ao);

                    float cnew = fmaf(fv, cr[p * 2 + e], iv * gv);
                    cr[p * 2 + e] = cnew;
                    hv[e] = ov * fast_tanh(cnew);
                }
                __half2 hh = __floats2half2_rn(hv[0], hv[1]);
                h2out[p] = *reinterpret_cast<u32*>(&hh);
            }
            *reinterpret_cast<uint2*>(g_PH + (size_t)s * PH_STEP + wIdx) =
                make_uint2(h2out[0], h2out[1]);
        }

        // ---- grid barrier: 8 spread counters, lane-parallel poll ----
        __syncthreads();
        __threadfence();
        if (w == 0) {
            if (lane == 0)
                atomicAdd(&g_bar[s * 256 + (blockIdx.x & 7) * 32], 1);
            int done;
            do {
                int v = (lane < 8)
                      ? *((volatile int*)&g_bar[s * 256 + lane * 32]) : 16;
                done = __all_sync(0xffffffffu, v >= 16);
            } while (!done);
        }
        __syncthreads();
        __threadfence();
    }
}

// Reset barrier counters for deterministic graph replay.
__global__ void reset_bar_kernel()
{
    g_bar[blockIdx.x * 256 + threadIdx.x] = 0;
}

// =========================================================================
// Logits: out[b][s][n] = h(fp16 PH) @ W_pred^T + b_pred via mma.
// =========================================================================
__global__ void __launch_bounds__(256, 1)
logits_mma_kernel(const float* __restrict__ bias, float* __restrict__ out)
{
    extern __shared__ uint4 wb[];      // 8192 uint4 = 128 KB

    const int tid  = threadIdx.x;
    const int lane = tid & 31;
    const int w    = tid >> 5;
    const int nb   = blockIdx.x;
    const int s    = blockIdx.y;
    const int grp  = lane >> 2;
    const int tig  = lane & 3;

    for (int i = tid; i < 8192; i += 256)
        wb[i] = g_WpPack[nb * 8192 + i];
    __syncthreads();

    const u32* ph   = g_PH + (size_t)s * PH_STEP;
    const int aBase = (w * 8 + grp) * 1024 + 4 * tig;

    float acc[8][4];
#pragma unroll
    for (int t = 0; t < 8; t++)
#pragma unroll
        for (int j = 0; j < 4; j++) acc[t][j] = 0.f;

#pragma unroll 2
    for (int it = 0; it < 64; it++) {
        uint4 a = *reinterpret_cast<const uint4*>(ph + aBase + it * 16);
#pragma unroll
        for (int q = 0; q < 4; q++) {
            uint4 wq = wb[it * 128 + q * 32 + lane];
            MMA16816(acc[2 * q],     a.x, a.y, a.z, a.w, wq.x, wq.y);
            MMA16816(acc[2 * q + 1], a.x, a.y, a.z, a.w, wq.z, wq.w);
        }
    }

    const int bL = w * 16 + grp;
    const int bH = bL + 8;
#pragma unroll
    for (int t = 0; t < 8; t++) {
        int col = nb * 64 + t * 8 + 2 * tig;
        float2 bz = *reinterpret_cast<const float2*>(bias + col);
        *reinterpret_cast<float2*>(out + (size_t)bL * NS * NC + (size_t)s * NC + col) =
            make_float2(acc[t][0] + bz.x, acc[t][1] + bz.y);
        *reinterpret_cast<float2*>(out + (size_t)bH * NS * NC + (size_t)s * NC + col) =
            make_float2(acc[t][2] + bz.x, acc[t][3] + bz.y);
    }
}

// =========================================================================
// kernel_launch: G gemm -> pack W_pred -> LSTM -> bar reset -> logits mma
// =========================================================================
extern "C" void kernel_launch(void* const* d_in, const int* in_sizes, int n_in,
                              void* d_out, int out_size)
{
    const int*   x      = (const int*)  d_in[0];
    const float* emb    = (const float*)d_in[1];
    const float* W_ih   = (const float*)d_in[2];
    const float* W_hh   = (const float*)d_in[3];
    const float* b_ih   = (const float*)d_in[4];
    const float* b_hh   = (const float*)d_in[5];
    const float* W_pred = (const float*)d_in[6];
    const float* b_pred = (const float*)d_in[7];
    float* out = (float*)d_out;

    float* Gp; cudaGetSymbolAddress((void**)&Gp, g_G);

    // 1) G = emb @ W_ih^T + b_ih + b_hh
    {
        dim3 grid(NC / 64, G4 / 64);
        gemm_nt_kernel<<<grid, 256>>>(emb, W_ih, b_ih, b_hh, Gp, NC, G4, DM);
    }

    // 2) pack W_pred into fp16 B-fragment order
    pack_wpred_kernel<<<256, 256>>>(W_pred);

    // 3) persistent tensor-core LSTM (single node)
    {
        const int smem_bytes = 65536 + 16384;   // wfrag 64 KB + split-K 16 KB
        cudaFuncSetAttribute(lstm_mma_kernel,
                             cudaFuncAttributeMaxDynamicSharedMemorySize, smem_bytes);
        lstm_mma_kernel<<<NCTA, 512, smem_bytes>>>(x, W_hh);
    }

    // 4) reset barrier counters for the next graph replay
    reset_bar_kernel<<<NS, 256>>>();

    // 5) logits via tensor cores
    {
        const int smem_bytes = 8192 * (int)sizeof(uint4);   // 128 KB
        cudaFuncSetAttribute(logits_mma_kernel,
                             cudaFuncAttributeMaxDynamicSharedMemorySize, smem_bytes);
        dim3 grid(8, NS);
        logits_mma_kernel<<<grid, 256, smem_bytes>>>(b_pred, out);
    }
}

// round 7
// speedup vs baseline: 4.6310x; 1.0077x over previous
#include <cuda_runtime.h>
#include <cuda_fp16.h>
#include <cstdint>
#include <math.h>

typedef unsigned int u32;

// Problem dims
#define DM   1024          // d_model
#define G4   4096          // 4*d_model
#define NB   128           // batch
#define NS   1024          // seq
#define NC   512           // n_classes
#define NCTA 128           // persistent CTAs (one per 8 d-values)

// PH layout: per step, 64 batch-pairs x 512 k2-slots x uint2 {h2[b], h2[b+8]}
// = 65536 u32 = 256 KB / step. Slot permutation makes one uint4 load at
// (pair*1024 + it*16 + 4*tig) yield the full m16n8k16 A-fragment.
#define PH_STEP 65536

// ---------------- device scratch (static, no allocation) ----------------
__device__ float g_G[NC * G4];              // 8 MB
__device__ u32   g_PH[NS * PH_STEP];        // 256 MB fp16 h history, fragment-packed
__device__ uint4 g_WpPack[8 * 64 * 4 * 32]; // 1 MB W_pred fp16 B-fragment order
__device__ int   g_bar[NS * 256];           // 8 spread counters/step (stride 32)

// =========================================================================
// fp32 NT GEMM for G: C[M,N] = A @ B^T + bias0 + bias1  (known-good)
// =========================================================================
__global__ void gemm_nt_kernel(const float* __restrict__ A,
                               const float* __restrict__ Bm,
                               const float* __restrict__ bias0,
                               const float* __restrict__ bias1,
                               float* __restrict__ Cout,
                               int M, int N, int K)
{
    __shared__ float As[16][64];
    __shared__ float Bs[16][64];

    const int tid = threadIdx.x;
    const int tx  = tid & 15;
    const int ty  = tid >> 4;
    const int mBase = blockIdx.x * 64;
    const int nBase = blockIdx.y * 64;

    const int la  = tid >> 2;
    const int lk  = (tid & 3) * 4;

    float acc[4][4];
#pragma unroll
    for (int i = 0; i < 4; i++)
#pragma unroll
        for (int j = 0; j < 4; j++) acc[i][j] = 0.f;

    for (int kc = 0; kc < K; kc += 16) {
        {
            float4 v = *reinterpret_cast<const float4*>(&A[(size_t)(mBase + la) * K + kc + lk]);
            As[lk + 0][la] = v.x; As[lk + 1][la] = v.y;
            As[lk + 2][la] = v.z; As[lk + 3][la] = v.w;
        }
        {
            float4 v = *reinterpret_cast<const float4*>(&Bm[(size_t)(nBase + la) * K + kc + lk]);
            Bs[lk + 0][la] = v.x; Bs[lk + 1][la] = v.y;
            Bs[lk + 2][la] = v.z; Bs[lk + 3][la] = v.w;
        }
        __syncthreads();

#pragma unroll
        for (int k = 0; k < 16; k++) {
            float4 a4 = *reinterpret_cast<const float4*>(&As[k][tx * 4]);
            float4 b4 = *reinterpret_cast<const float4*>(&Bs[k][ty * 4]);
            float a[4] = {a4.x, a4.y, a4.z, a4.w};
            float b[4] = {b4.x, b4.y, b4.z, b4.w};
#pragma unroll
            for (int i = 0; i < 4; i++)
#pragma unroll
                for (int j = 0; j < 4; j++)
                    acc[i][j] = fmaf(a[i], b[j], acc[i][j]);
        }
        __syncthreads();
    }

#pragma unroll
    for (int i = 0; i < 4; i++) {
        int row = mBase + tx * 4 + i;
#pragma unroll
        for (int j = 0; j < 4; j++) {
            int col = nBase + ty * 4 + j;
            Cout[(size_t)row * N + col] = acc[i][j] + bias0[col] + bias1[col];
        }
    }
}

// ---- fast, saturating-safe activations ----
__device__ __forceinline__ float fast_sigmoid(float x) {
    return 1.f / (1.f + __expf(-x));
}
__device__ __forceinline__ float fast_tanh(float x) {
    return 1.f - 2.f / (1.f + __expf(2.f * x));
}

#define MMA16816(C, A0, A1, A2, A3, B0, B1)                                   \
    asm volatile(                                                             \
        "mma.sync.aligned.m16n8k16.row.col.f32.f16.f16.f32 "                  \
        "{%0,%1,%2,%3}, {%4,%5,%6,%7}, {%8,%9}, {%0,%1,%2,%3};"               \
        : "+f"(C[0]), "+f"(C[1]), "+f"(C[2]), "+f"(C[3])                      \
        : "r"(A0), "r"(A1), "r"(A2), "r"(A3), "r"(B0), "r"(B1))

// =========================================================================
// Pack W_pred (fp32) -> g_WpPack (fp16, B-fragment order).
// =========================================================================
__global__ void pack_wpred_kernel(const float* __restrict__ Wp)
{
    int idx  = blockIdx.x * 256 + threadIdx.x;     // 0..65535
    int lane = idx & 31;
    int q    = (idx >> 5) & 3;
    int it   = (idx >> 7) & 63;
    int nb   = idx >> 13;

    u32 v[4];
#pragma unroll
    for (int h = 0; h < 2; h++) {
        int t = 2 * q + h;
        int n = nb * 64 + t * 8 + (lane >> 2);
        const float* row = Wp + (size_t)n * DM;
        int j0 = it * 8 + (lane & 3);
        int j1 = j0 + 4;
        __half2 p0 = __floats2half2_rn(row[2 * j0], row[2 * j0 + 1]);
        __half2 p1 = __floats2half2_rn(row[2 * j1], row[2 * j1 + 1]);
        v[2 * h + 0] = *reinterpret_cast<u32*>(&p0);
        v[2 * h + 1] = *reinterpret_cast<u32*>(&p1);
    }
    g_WpPack[idx] = make_uint4(v[0], v[1], v[2], v[3]);
}

// =========================================================================
// Persistent tensor-core LSTM: 128 CTAs x 512 threads (16 warps).
// Warp w (0..7): batches [16w,16w+16), K in [0,512).
// Warp w (8..15): same batches as w-8, K in [512,1024); split-K reduced in smem.
// A-fragments: 1 LDG.128/iter from fragment-packed g_PH[s-1]. W in smem.
// Thread-local cell update (warps 0..7), c in registers, G gather hoisted
// above the mma loop.
// =========================================================================
__global__ void __launch_bounds__(512, 1)
lstm_mma_kernel(const int* __restrict__ x,
                const float* __restrict__ Whh)
{
    extern __shared__ char smem_raw[];
    uint4* wfrag = reinterpret_cast<uint4*>(smem_raw);            // 4096 uint4 = 64 KB
    float* red   = reinterpret_cast<float*>(smem_raw + 65536);    // 4096 f  = 16 KB

    const int tid  = threadIdx.x;
    const int lane = tid & 31;
    const int w    = tid >> 5;          // 0..15
    const int bg   = w & 7;             // batch group
    const int kh   = w >> 3;            // K half
    const int d0   = blockIdx.x * 8;
    const int tig  = lane & 3;
    const int grp  = lane >> 2;

    // ---- one-time: W_hh slice -> fp16 B-fragment order in smem ----
    for (int e = tid; e < 64 * 2 * 32; e += 512) {
        int l   = e & 31;
        int nth = (e >> 5) & 1;
        int it  = e >> 6;
        int k0  = it * 16 + 2 * (l & 3);
        u32 v[4];
#pragma unroll
        for (int h = 0; h < 2; h++) {
            int nt   = 2 * nth + h;                  // gate index 0..3
            int grow = nt * DM + d0 + (l >> 2);      // gate-major W_hh row
            const float* Wr = &Whh[(size_t)grow * DM];
            __half2 p0 = __floats2half2_rn(Wr[k0],     Wr[k0 + 1]);
            __half2 p1 = __floats2half2_rn(Wr[k0 + 8], Wr[k0 + 9]);
            v[h * 2 + 0] = *reinterpret_cast<u32*>(&p0);
            v[h * 2 + 1] = *reinterpret_cast<u32*>(&p1);
        }
        wfrag[e] = make_uint4(v[0], v[1], v[2], v[3]);
    }
    __syncthreads();

    // ---- persistent per-thread state ----
    const int pair = bg * 8 + grp;
    const int b_lo = bg * 16 + grp;
    const int b_hi = b_lo + 8;
    const int dd   = d0 + 2 * tig;
    // PH write slot for k2 = dd/2 (warps 0..7 only)
    const int k2   = (d0 >> 1) + tig;
    const int p8   = k2 & 7;
    const int slot = (p8 < 4) ? (2 * p8) : (2 * (p8 - 4) + 1);
    const int wIdx  = pair * 1024 + ((k2 >> 3) * 8 + slot) * 2;
    const int aBase = pair * 1024 + 4 * tig;
    const int rIdx  = (bg * 32 + lane) * 16;   // split-K exchange slot

    float cr[4] = {0.f, 0.f, 0.f, 0.f};

    for (int s = 0; s < NS; s++) {
        float acc[4][4];
#pragma unroll
        for (int i = 0; i < 4; i++)
#pragma unroll
            for (int j = 0; j < 4; j++) acc[i][j] = 0.f;

        // ---- hoisted gather: x and G rows (depend only on s) ----
        float gi[2][2], gf[2][2], gg[2][2], go[2][2];
        if (kh == 0) {
            const int xlo = __ldg(&x[s * NB + b_lo]);
            const int xhi = __ldg(&x[s * NB + b_hi]);
            const float* GpL = &g_G[(size_t)xlo * G4 + dd];
            const float* GpH = &g_G[(size_t)xhi * G4 + dd];
#pragma unroll
            for (int p = 0; p < 2; p++) {
                const float* Gp = p ? GpH : GpL;
                float2 a0 = *reinterpret_cast<const float2*>(Gp + 0 * DM);
                float2 a1 = *reinterpret_cast<const float2*>(Gp + 1 * DM);
                float2 a2 = *reinterpret_cast<const float2*>(Gp + 2 * DM);
                float2 a3 = *reinterpret_cast<const float2*>(Gp + 3 * DM);
                gi[p][0] = a0.x; gi[p][1] = a0.y;
                gf[p][0] = a1.x; gf[p][1] = a1.y;
                gg[p][0] = a2.x; gg[p][1] = a2.y;
                go[p][0] = a3.x; go[p][1] = a3.y;
            }
        }

        if (s > 0) {
            const u32* ph = g_PH + (size_t)(s - 1) * PH_STEP;
            const int it0 = kh * 32;
#pragma unroll 4
            for (int i = 0; i < 32; i++) {
                const int it = it0 + i;
                uint4 w01 = wfrag[(it * 2 + 0) * 32 + lane];
                uint4 w23 = wfrag[(it * 2 + 1) * 32 + lane];
                uint4 a = *reinterpret_cast<const uint4*>(ph + aBase + it * 16);
                MMA16816(acc[0], a.x, a.y, a.z, a.w, w01.x, w01.y);
                MMA16816(acc[1], a.x, a.y, a.z, a.w, w01.z, w01.w);
                MMA16816(acc[2], a.x, a.y, a.z, a.w, w23.x, w23.y);
                MMA16816(acc[3], a.x, a.y, a.z, a.w, w23.z, w23.w);
            }
        }

        // ---- split-K reduction: warps 8..15 publish, warps 0..7 add ----
        if (kh == 1) {
            float* r = red + rIdx;
#pragma unroll
            for (int t = 0; t < 4; t++)
                *reinterpret_cast<float4*>(r + t * 4) =
                    make_float4(acc[t][0], acc[t][1], acc[t][2], acc[t][3]);
        }
        __syncthreads();

        if (kh == 0) {
            const float* r = red + rIdx;
#pragma unroll
            for (int t = 0; t < 4; t++) {
                float4 v = *reinterpret_cast<const float4*>(r + t * 4);
                acc[t][0] += v.x; acc[t][1] += v.y;
                acc[t][2] += v.z; acc[t][3] += v.w;
            }

            // ---- thread-local LSTM cell update ----
            u32 h2out[2];
#pragma unroll
            for (int p = 0; p < 2; p++) {
                float hv[2];
#pragma unroll
                for (int e = 0; e < 2; e++) {
                    float ai = acc[0][p * 2 + e] + gi[p][e];
                    float af = acc[1][p * 2 + e] + gf[p][e];
                    float ag = acc[2][p * 2 + e] + gg[p][e];
                    float ao = acc[3][p * 2 + e] + go[p][e];

                    float iv = fast_sigmoid(ai);
                    float fv = fast_sigmoid(af);
                    float gv = fast_tanh(ag);
                    float ov = fast_sigmoid(ao);

                    float cnew = fmaf(fv, cr[p * 2 + e], iv * gv);
                    cr[p * 2 + e] = cnew;
                    hv[e] = ov * fast_tanh(cnew);
                }
                __half2 hh = __floats2half2_rn(hv[0], hv[1]);
                h2out[p] = *reinterpret_cast<u32*>(&hh);
            }
            *reinterpret_cast<uint2*>(g_PH + (size_t)s * PH_STEP + wIdx) =
                make_uint2(h2out[0], h2out[1]);
        }

        // ---- grid barrier: 8 spread counters, lane-parallel poll ----
        __syncthreads();
        __threadfence();
        if (w == 0) {
            if (lane == 0)
                atomicAdd(&g_bar[s * 256 + (blockIdx.x & 7) * 32], 1);
            int done;
            do {
                int v = (lane < 8)
                      ? *((volatile int*)&g_bar[s * 256 + lane * 32]) : 16;
                done = __all_sync(0xffffffffu, v >= 16);
            } while (!done);
        }
        __syncthreads();
        __threadfence();
    }
}

// Reset barrier counters for deterministic graph replay.
__global__ void reset_bar_kernel()
{
    g_bar[blockIdx.x * 256 + threadIdx.x] = 0;
}

// =========================================================================
// Logits: out[b][s][n] = h(fp16 PH) @ W_pred^T + b_pred via mma.
// =========================================================================
__global__ void __launch_bounds__(256, 1)
logits_mma_kernel(const float* __restrict__ bias, float* __restrict__ out)
{
    extern __shared__ uint4 wb[];      // 8192 uint4 = 128 KB

    const int tid  = threadIdx.x;
    const int lane = tid & 31;
    const int w    = tid >> 5;
    const int nb   = blockIdx.x;
    const int s    = blockIdx.y;
    const int grp  = lane >> 2;
    const int tig  = lane & 3;

    for (int i = tid; i < 8192; i += 256)
        wb[i] = g_WpPack[nb * 8192 + i];
    __syncthreads();

    const u32* ph   = g_PH + (size_t)s * PH_STEP;
    const int aBase = (w * 8 + grp) * 1024 + 4 * tig;

    float acc[8][4];
#pragma unroll
    for (int t = 0; t < 8; t++)
#pragma unroll
        for (int j = 0; j < 4; j++) acc[t][j] = 0.f;

#pragma unroll 2
    for (int it = 0; it < 64; it++) {
        uint4 a = *reinterpret_cast<const uint4*>(ph + aBase + it * 16);
#pragma unroll
        for (int q = 0; q < 4; q++) {
            uint4 wq = wb[it * 128 + q * 32 + lane];
            MMA16816(acc[2 * q],     a.x, a.y, a.z, a.w, wq.x, wq.y);
            MMA16816(acc[2 * q + 1], a.x, a.y, a.z, a.w, wq.z, wq.w);
        }
    }

    const int bL = w * 16 + grp;
    const int bH = bL + 8;
#pragma unroll
    for (int t = 0; t < 8; t++) {
        int col = nb * 64 + t * 8 + 2 * tig;
        float2 bz = *reinterpret_cast<const float2*>(bias + col);
        *reinterpret_cast<float2*>(out + (size_t)bL * NS * NC + (size_t)s * NC + col) =
            make_float2(acc[t][0] + bz.x, acc[t][1] + bz.y);
        *reinterpret_cast<float2*>(out + (size_t)bH * NS * NC + (size_t)s * NC + col) =
            make_float2(acc[t][2] + bz.x, acc[t][3] + bz.y);
    }
}

// =========================================================================
// kernel_launch: G gemm -> pack W_pred -> LSTM -> bar reset -> logits mma
// =========================================================================
extern "C" void kernel_launch(void* const* d_in, const int* in_sizes, int n_in,
                              void* d_out, int out_size)
{
    const int*   x      = (const int*)  d_in[0];
    const float* emb    = (const float*)d_in[1];
    const float* W_ih   = (const float*)d_in[2];
    const float* W_hh   = (const float*)d_in[3];
    const float* b_ih   = (const float*)d_in[4];
    const float* b_hh   = (const float*)d_in[5];
    const float* W_pred = (const float*)d_in[6];
    const float* b_pred = (const float*)d_in[7];
    float* out = (float*)d_out;

    float* Gp; cudaGetSymbolAddress((void**)&Gp, g_G);

    // 1) G = emb @ W_ih^T + b_ih + b_hh
    {
        dim3 grid(NC / 64, G4 / 64);
        gemm_nt_kernel<<<grid, 256>>>(emb, W_ih, b_ih, b_hh, Gp, NC, G4, DM);
    }

    // 2) pack W_pred into fp16 B-fragment order
    pack_wpred_kernel<<<256, 256>>>(W_pred);

    // 3) persistent tensor-core LSTM (single node)
    {
        const int smem_bytes = 65536 + 16384;   // wfrag 64 KB + split-K 16 KB
        cudaFuncSetAttribute(lstm_mma_kernel,
                             cudaFuncAttributeMaxDynamicSharedMemorySize, smem_bytes);
        lstm_mma_kernel<<<NCTA, 512, smem_bytes>>>(x, W_hh);
    }

    // 4) reset barrier counters for the next graph replay
    reset_bar_kernel<<<NS, 256>>>();

    // 5) logits via tensor cores
    {
        const int smem_bytes = 8192 * (int)sizeof(uint4);   // 128 KB
        cudaFuncSetAttribute(logits_mma_kernel,
                             cudaFuncAttributeMaxDynamicSharedMemorySize, smem_bytes);
        dim3 grid(8, NS);
        logits_mma_kernel<<<grid, 256, smem_bytes>>>(b_pred, out);
    }
}

// round 10
// speedup vs baseline: 4.8767x; 1.0531x over previous
#include <cuda_runtime.h>
#include <cuda_fp16.h>
#include <cstdint>
#include <math.h>

typedef unsigned int u32;

#define DM   1024
#define G4   4096
#define NB   128
#define NS   1024
#define NC   512
#define NCTA 128
#define PH_STEP 65536

// ---------------- device scratch (static, no allocation) ----------------
__device__ float g_G[NC * G4];              // 8 MB
__device__ u32   g_PH[NS * PH_STEP];        // 256 MB fp16 h history, fragment-packed
__device__ uint4 g_WpPack[8 * 64 * 4 * 32]; // 1 MB W_pred fp16 B-fragment order
__device__ int   g_bar[NS * 256];           // 8 spread counters/step (stride 32)

// ============ fp32 NT GEMM for G (known-good) ============
__global__ void gemm_nt_kernel(const float* __restrict__ A, const float* __restrict__ Bm,
                               const float* __restrict__ bias0, const float* __restrict__ bias1,
                               float* __restrict__ Cout, int M, int N, int K)
{
    __shared__ float As[16][64];
    __shared__ float Bs[16][64];
    const int tid = threadIdx.x;
    const int tx = tid & 15, ty = tid >> 4;
    const int mBase = blockIdx.x * 64, nBase = blockIdx.y * 64;
    const int la = tid >> 2, lk = (tid & 3) * 4;

    float acc[4][4];
#pragma unroll
    for (int i = 0; i < 4; i++)
#pragma unroll
        for (int j = 0; j < 4; j++) acc[i][j] = 0.f;

    for (int kc = 0; kc < K; kc += 16) {
        {
            float4 v = *reinterpret_cast<const float4*>(&A[(size_t)(mBase + la) * K + kc + lk]);
            As[lk + 0][la] = v.x; As[lk + 1][la] = v.y; As[lk + 2][la] = v.z; As[lk + 3][la] = v.w;
        }
        {
            float4 v = *reinterpret_cast<const float4*>(&Bm[(size_t)(nBase + la) * K + kc + lk]);
            Bs[lk + 0][la] = v.x; Bs[lk + 1][la] = v.y; Bs[lk + 2][la] = v.z; Bs[lk + 3][la] = v.w;
        }
        __syncthreads();
#pragma unroll
        for (int k = 0; k < 16; k++) {
            float4 a4 = *reinterpret_cast<const float4*>(&As[k][tx * 4]);
            float4 b4 = *reinterpret_cast<const float4*>(&Bs[k][ty * 4]);
            float a[4] = {a4.x, a4.y, a4.z, a4.w};
            float b[4] = {b4.x, b4.y, b4.z, b4.w};
#pragma unroll
            for (int i = 0; i < 4; i++)
#pragma unroll
                for (int j = 0; j < 4; j++)
                    acc[i][j] = fmaf(a[i], b[j], acc[i][j]);
        }
        __syncthreads();
    }
#pragma unroll
    for (int i = 0; i < 4; i++) {
        int row = mBase + tx * 4 + i;
#pragma unroll
        for (int j = 0; j < 4; j++) {
            int col = nBase + ty * 4 + j;
            Cout[(size_t)row * N + col] = acc[i][j] + bias0[col] + bias1[col];
        }
    }
}

// ---- fast, saturating-safe activations ----
__device__ __forceinline__ float fast_sigmoid(float x) { return 1.f / (1.f + __expf(-x)); }
__device__ __forceinline__ float fast_tanh(float x)    { return 1.f - 2.f / (1.f + __expf(2.f * x)); }

#define MMA16816(C, A0, A1, A2, A3, B0, B1)                                   \
    asm volatile(                                                             \
        "mma.sync.aligned.m16n8k16.row.col.f32.f16.f16.f32 "                  \
        "{%0,%1,%2,%3}, {%4,%5,%6,%7}, {%8,%9}, {%0,%1,%2,%3};"               \
        : "+f"(C[0]), "+f"(C[1]), "+f"(C[2]), "+f"(C[3])                      \
        : "r"(A0), "r"(A1), "r"(A2), "r"(A3), "r"(B0), "r"(B1))

// ============ pack W_pred -> fp16 B-fragment order (known-good) ============
__global__ void pack_wpred_kernel(const float* __restrict__ Wp)
{
    int idx = blockIdx.x * 256 + threadIdx.x;
    int lane = idx & 31, q = (idx >> 5) & 3, it = (idx >> 7) & 63, nb = idx >> 13;
    u32 v[4];
#pragma unroll
    for (int h = 0; h < 2; h++) {
        int t = 2 * q + h;
        int n = nb * 64 + t * 8 + (lane >> 2);
        const float* row = Wp + (size_t)n * DM;
        int j0 = it * 8 + (lane & 3), j1 = j0 + 4;
        __half2 p0 = __floats2half2_rn(row[2 * j0], row[2 * j0 + 1]);
        __half2 p1 = __floats2half2_rn(row[2 * j1], row[2 * j1 + 1]);
        v[2 * h + 0] = *reinterpret_cast<u32*>(&p0);
        v[2 * h + 1] = *reinterpret_cast<u32*>(&p1);
    }
    g_WpPack[idx] = make_uint4(v[0], v[1], v[2], v[3]);
}

// =========================================================================
// Persistent LSTM: 128 CTAs x 256 threads (8 warps).
// Warp w = (bh = w&1 batch-half, q = w>>1 k-quarter): M=64, K=256, all N=32.
// W_hh fragments live in REGISTERS (128 u32/thread) for all 1024 steps —
// zero per-step W smem traffic. Split-K=4 partials exchanged via padded smem.
// Cell update: R5's proven thread ownership (b_lo/b_hi pair, dd=2 d's),
// c in registers, fragment-packed PH write.
// =========================================================================
#define RSTRIDE 36
__global__ void __launch_bounds__(256, 1)
lstm_mma_kernel(const int* __restrict__ x, const float* __restrict__ Whh)
{
    extern __shared__ float red[];     // 4 quarters * 128 rows * RSTRIDE floats

    const int tid  = threadIdx.x;
    const int lane = tid & 31;
    const int w    = tid >> 5;         // 0..7
    const int bh   = w & 1;            // batch half
    const int q    = w >> 1;           // k quarter
    const int d0   = blockIdx.x * 8;
    const int tig  = lane & 3;
    const int grp  = lane >> 2;

    // ---- one-time: W_hh fragments -> registers (proven fragment math) ----
    u32 wreg[128];
    {
        const int kbase = q * 256 + 2 * tig;
#pragma unroll
        for (int it = 0; it < 16; it++) {
#pragma unroll
            for (int n = 0; n < 4; n++) {
                const float* Wr = Whh + (size_t)(n * DM + d0 + grp) * DM + kbase + it * 16;
                __half2 p0 = __floats2half2_rn(Wr[0], Wr[1]);
                __half2 p1 = __floats2half2_rn(Wr[8], Wr[9]);
                wreg[it * 8 + n * 2 + 0] = *reinterpret_cast<u32*>(&p0);
                wreg[it * 8 + n * 2 + 1] = *reinterpret_cast<u32*>(&p1);
            }
        }
    }

    // ---- cell-update ownership (R5 scheme, proven) ----
    const int b_lo = w * 16 + grp;
    const int b_hi = b_lo + 8;
    const int dd   = d0 + 2 * tig;
    const int k2   = (d0 >> 1) + tig;
    const int p8   = k2 & 7;
    const int slot = (p8 < 4) ? (2 * p8) : (2 * (p8 - 4) + 1);
    const int wIdx = (w * 8 + grp) * 1024 + ((k2 >> 3) * 8 + slot) * 2;

    // ---- A-fragment read bases for the 4 mtiles of this warp ----
    int aBase[4];
#pragma unroll
    for (int t = 0; t < 4; t++)
        aBase[t] = ((4 * bh + t) * 8 + grp) * 1024 + 4 * tig + q * 256;

    float cr[4] = {0.f, 0.f, 0.f, 0.f};

    for (int s = 0; s < NS; s++) {
        const int xlo = __ldg(&x[s * NB + b_lo]);
        const int xhi = __ldg(&x[s * NB + b_hi]);

        float acc[4][4][4];            // [mtile][ntile=gate][c]
#pragma unroll
        for (int t = 0; t < 4; t++)
#pragma unroll
            for (int n = 0; n < 4; n++)
#pragma unroll
                for (int j = 0; j < 4; j++) acc[t][n][j] = 0.f;

        if (s > 0) {
            const u32* ph = g_PH + (size_t)(s - 1) * PH_STEP;
#pragma unroll
            for (int it = 0; it < 16; it++) {
                uint4 a0 = *reinterpret_cast<const uint4*>(ph + aBase[0] + it * 16);
                uint4 a1 = *reinterpret_cast<const uint4*>(ph + aBase[1] + it * 16);
                uint4 a2 = *reinterpret_cast<const uint4*>(ph + aBase[2] + it * 16);
                uint4 a3 = *reinterpret_cast<const uint4*>(ph + aBase[3] + it * 16);
#pragma unroll
                for (int n = 0; n < 4; n++) {
                    u32 w0 = wreg[it * 8 + 2 * n], w1 = wreg[it * 8 + 2 * n + 1];
                    MMA16816(acc[0][n], a0.x, a0.y, a0.z, a0.w, w0, w1);
                    MMA16816(acc[1][n], a1.x, a1.y, a1.z, a1.w, w0, w1);
                    MMA16816(acc[2][n], a2.x, a2.y, a2.z, a2.w, w0, w1);
                    MMA16816(acc[3][n], a3.x, a3.y, a3.z, a3.w, w0, w1);
                }
            }
        }

        // ---- publish split-K partials: red[q][row][col], padded stride ----
        {
            float* rq = red + q * (128 * RSTRIDE);
#pragma unroll
            for (int t = 0; t < 4; t++) {
                int r0 = 64 * bh + 16 * t + grp;
#pragma unroll
                for (int n = 0; n < 4; n++) {
                    int col = 8 * n + 2 * tig;
                    *reinterpret_cast<float2*>(rq + r0 * RSTRIDE + col) =
                        make_float2(acc[t][n][0], acc[t][n][1]);
                    *reinterpret_cast<float2*>(rq + (r0 + 8) * RSTRIDE + col) =
                        make_float2(acc[t][n][2], acc[t][n][3]);
                }
            }
        }
        __syncthreads();

        // ---- reduce 4 quarters + thread-local LSTM cell update ----
        {
            const float* GL = g_G + (size_t)xlo * G4 + dd;
            const float* GH = g_G + (size_t)xhi * G4 + dd;
            float gl[4][2], gh[4][2];
#pragma unroll
            for (int g = 0; g < 4; g++) {
                float2 v = *reinterpret_cast<const float2*>(GL + g * DM);
                gl[g][0] = v.x; gl[g][1] = v.y;
                float2 u = *reinterpret_cast<const float2*>(GH + g * DM);
                gh[g][0] = u.x; gh[g][1] = u.y;
            }

            float sum[2][4][2];        // [p(b_lo/b_hi)][gate][e]
#pragma unroll
            for (int g = 0; g < 4; g++) {
                float sLx = 0.f, sLy = 0.f, sHx = 0.f, sHy = 0.f;
#pragma unroll
                for (int qq = 0; qq < 4; qq++) {
                    const float* rq = red + qq * (128 * RSTRIDE);
                    float2 vL = *reinterpret_cast<const float2*>(rq + b_lo * RSTRIDE + 8 * g + 2 * tig);
                    float2 vH = *reinterpret_cast<const float2*>(rq + b_hi * RSTRIDE + 8 * g + 2 * tig);
                    sLx += vL.x; sLy += vL.y; sHx += vH.x; sHy += vH.y;
                }
                sum[0][g][0] = sLx; sum[0][g][1] = sLy;
                sum[1][g][0] = sHx; sum[1][g][1] = sHy;
            }

            u32 h2out[2];
#pragma unroll
            for (int p = 0; p < 2; p++) {
                float hv[2];
#pragma unroll
                for (int e = 0; e < 2; e++) {
                    float ai = sum[p][0][e] + (p ? gh[0][e] : gl[0][e]);
                    float af = sum[p][1][e] + (p ? gh[1][e] : gl[1][e]);
                    float ag = sum[p][2][e] + (p ? gh[2][e] : gl[2][e]);
                    float ao = sum[p][3][e] + (p ? gh[3][e] : gl[3][e]);

                    float iv = fast_sigmoid(ai);
                    float fv = fast_sigmoid(af);
                    float gv = fast_tanh(ag);
                    float ov = fast_sigmoid(ao);

                    float cnew = fmaf(fv, cr[p * 2 + e], iv * gv);
                    cr[p * 2 + e] = cnew;
                    hv[e] = ov * fast_tanh(cnew);
                }
                __half2 hh = __floats2half2_rn(hv[0], hv[1]);
                h2out[p] = *reinterpret_cast<u32*>(&hh);
            }
            *reinterpret_cast<uint2*>(g_PH + (size_t)s * PH_STEP + wIdx) =
                make_uint2(h2out[0], h2out[1]);
        }

        // ---- grid barrier: 8 spread counters, lane-parallel poll (proven) ----
        __syncthreads();
        __threadfence();
        if (w == 0) {
            if (lane == 0)
                atomicAdd(&g_bar[s * 256 + (blockIdx.x & 7) * 32], 1);
            int done;
            do {
                int v = (lane < 8)
                      ? *((volatile int*)&g_bar[s * 256 + lane * 32]) : 16;
                done = __all_sync(0xffffffffu, v >= 16);
            } while (!done);
        }
        __syncthreads();
        __threadfence();
    }
}

// Reset barrier counters for deterministic graph replay.
__global__ void reset_bar_kernel()
{
    g_bar[blockIdx.x * 256 + threadIdx.x] = 0;
}

// ============ logits: PH(fp16) @ W_pred^T + bias via warp mma (known-good) ============
__global__ void __launch_bounds__(256, 1)
logits_mma_kernel(const float* __restrict__ bias, float* __restrict__ out)
{
    extern __shared__ uint4 wb[];      // 8192 uint4 = 128 KB
    const int tid = threadIdx.x;
    const int lane = tid & 31, w = tid >> 5;
    const int nb = blockIdx.x, s = blockIdx.y;
    const int grp = lane >> 2, tig = lane & 3;

    for (int i = tid; i < 8192; i += 256) wb[i] = g_WpPack[nb * 8192 + i];
    __syncthreads();

    const u32* ph   = g_PH + (size_t)s * PH_STEP;
    const int aBase = (w * 8 + grp) * 1024 + 4 * tig;

    float acc[8][4];
#pragma unroll
    for (int t = 0; t < 8; t++)
#pragma unroll
        for (int j = 0; j < 4; j++) acc[t][j] = 0.f;

#pragma unroll 2
    for (int it = 0; it < 64; it++) {
        uint4 a = *reinterpret_cast<const uint4*>(ph + aBase + it * 16);
#pragma unroll
        for (int qq = 0; qq < 4; qq++) {
            uint4 wq = wb[it * 128 + qq * 32 + lane];
            MMA16816(acc[2 * qq],     a.x, a.y, a.z, a.w, wq.x, wq.y);
            MMA16816(acc[2 * qq + 1], a.x, a.y, a.z, a.w, wq.z, wq.w);
        }
    }

    const int bL = w * 16 + grp, bH = bL + 8;
#pragma unroll
    for (int t = 0; t < 8; t++) {
        int col = nb * 64 + t * 8 + 2 * tig;
        float2 bz = *reinterpret_cast<const float2*>(bias + col);
        *reinterpret_cast<float2*>(out + (size_t)bL * NS * NC + (size_t)s * NC + col) =
            make_float2(acc[t][0] + bz.x, acc[t][1] + bz.y);
        *reinterpret_cast<float2*>(out + (size_t)bH * NS * NC + (size_t)s * NC + col) =
            make_float2(acc[t][2] + bz.x, acc[t][3] + bz.y);
    }
}

// =========================================================================
extern "C" void kernel_launch(void* const* d_in, const int* in_sizes, int n_in,
                              void* d_out, int out_size)
{
    const int*   x      = (const int*)  d_in[0];
    const float* emb    = (const float*)d_in[1];
    const float* W_ih   = (const float*)d_in[2];
    const float* W_hh   = (const float*)d_in[3];
    const float* b_ih   = (const float*)d_in[4];
    const float* b_hh   = (const float*)d_in[5];
    const float* W_pred = (const float*)d_in[6];
    const float* b_pred = (const float*)d_in[7];
    float* out = (float*)d_out;

    float* Gp; cudaGetSymbolAddress((void**)&Gp, g_G);

    // 1) G = emb @ W_ih^T + b_ih + b_hh
    {
        dim3 grid(NC / 64, G4 / 64);
        gemm_nt_kernel<<<grid, 256>>>(emb, W_ih, b_ih, b_hh, Gp, NC, G4, DM);
    }
    // 2) pack W_pred
    pack_wpred_kernel<<<256, 256>>>(W_pred);
    // 3) persistent LSTM (W in registers, split-K=4)
    {
        const int smem_bytes = 4 * 128 * RSTRIDE * (int)sizeof(float);  // 73728
        cudaFuncSetAttribute(lstm_mma_kernel,
                             cudaFuncAttributeMaxDynamicSharedMemorySize, smem_bytes);
        lstm_mma_kernel<<<NCTA, 256, smem_bytes>>>(x, W_hh);
    }
    // 4) reset barrier counters
    reset_bar_kernel<<<NS, 256>>>();
    // 5) logits
    {
        const int smem_bytes = 8192 * (int)sizeof(uint4);
        cudaFuncSetAttribute(logits_mma_kernel,
                             cudaFuncAttributeMaxDynamicSharedMemorySize, smem_bytes);
        dim3 grid(8, NS);
        logits_mma_kernel<<<grid, 256, smem_bytes>>>(b_pred, out);
    }
}